// round 9
// baseline (speedup 1.0000x reference)
#include <cuda_runtime.h>
#include <cuda_fp16.h>
#include <cstdint>

#define M_TOTAL 65536
#define W_STRIDE 512

__device__ float g_bufA[256 * 256];
__device__ float g_bufB[256 * 256];
__device__ float g_scale[1];
__device__ unsigned g_bar;
__device__ __align__(16) __half g_whi[256 * 256];
__device__ __align__(16) __half g_wlo[256 * 256];

__device__ __forceinline__ float tanh_acc(float z) {
    float e = __expf(2.0f * z);
    return 1.0f - 2.0f / (e + 1.0f);
}
__device__ __forceinline__ uint32_t smem_u32(const void* p) {
    uint32_t a;
    asm("{ .reg .u64 t; cvta.to.shared.u64 t, %1; cvt.u32.u64 %0, t; }" : "=r"(a) : "l"(p));
    return a;
}
#define CP_ASYNC16(dst, src) \
    asm volatile("cp.async.cg.shared.global [%0], [%1], 16;" :: "r"(dst), "l"(src) : "memory")
#define CP_COMMIT() asm volatile("cp.async.commit_group;" ::: "memory")
#define CP_WAIT1()  asm volatile("cp.async.wait_group 1;" ::: "memory")
#define LDM_X4(r0, r1, r2, r3, a) \
    asm volatile("ldmatrix.sync.aligned.m8n8.x4.shared.b16 {%0,%1,%2,%3}, [%4];" \
                 : "=r"(r0), "=r"(r1), "=r"(r2), "=r"(r3) : "r"(a))
#define STS128(a, r0, r1, r2, r3) \
    asm volatile("st.shared.v4.b32 [%0], {%1,%2,%3,%4};" :: "r"(a), "r"(r0), "r"(r1), "r"(r2), "r"(r3) : "memory")
__device__ __forceinline__ void mma16816(float* c, const uint32_t* a, const uint32_t* b) {
    asm volatile(
        "mma.sync.aligned.m16n8k16.row.col.f32.f16.f16.f32 "
        "{%0,%1,%2,%3},{%4,%5,%6,%7},{%8,%9},{%0,%1,%2,%3};"
        : "+f"(c[0]), "+f"(c[1]), "+f"(c[2]), "+f"(c[3])
        : "r"(a[0]), "r"(a[1]), "r"(a[2]), "r"(a[3]), "r"(b[0]), "r"(b[1]));
}
__device__ __forceinline__ void split8(const float* f, uint32_t* hi, uint32_t* lo) {
#pragma unroll
    for (int p = 0; p < 4; p++) {
        const __half h0 = __float2half_rn(f[2 * p]);
        const __half h1 = __float2half_rn(f[2 * p + 1]);
        const __half l0 = __float2half_rn(f[2 * p] - __half2float(h0));
        const __half l1 = __float2half_rn(f[2 * p + 1] - __half2float(h1));
        hi[p] = (uint32_t)*(const uint16_t*)&h0 | ((uint32_t)*(const uint16_t*)&h1 << 16);
        lo[p] = (uint32_t)*(const uint16_t*)&l0 | ((uint32_t)*(const uint16_t*)&l1 << 16);
    }
}

// ---- Kernel 1: gram G = W W^T (full 512 cols) + W fp16 hi/lo split ----
__global__ __launch_bounds__(256) void prep_kernel(const float* __restrict__ W) {
    if (blockIdx.x < 64) {
        __shared__ float As[32][33], Bs[32][33];
        const int i0 = (blockIdx.x >> 3) * 32, j0 = (blockIdx.x & 7) * 32;
        const int tid = threadIdx.x;
        const int lr = tid >> 3, lc = (tid & 7) * 4;
        const int ty = tid >> 4, tx = tid & 15;
        float a00 = 0, a01 = 0, a10 = 0, a11 = 0;
        for (int kt = 0; kt < 512; kt += 32) {
            float4 av = *(const float4*)&W[(i0 + lr) * W_STRIDE + kt + lc];
            float4 bv = *(const float4*)&W[(j0 + lr) * W_STRIDE + kt + lc];
            As[lr][lc] = av.x; As[lr][lc + 1] = av.y; As[lr][lc + 2] = av.z; As[lr][lc + 3] = av.w;
            Bs[lr][lc] = bv.x; Bs[lr][lc + 1] = bv.y; Bs[lr][lc + 2] = bv.z; Bs[lr][lc + 3] = bv.w;
            __syncthreads();
#pragma unroll
            for (int k = 0; k < 32; k++) {
                float x0 = As[2 * ty][k], x1 = As[2 * ty + 1][k];
                float y0 = Bs[2 * tx][k], y1 = Bs[2 * tx + 1][k];
                a00 = fmaf(x0, y0, a00); a01 = fmaf(x0, y1, a01);
                a10 = fmaf(x1, y0, a10); a11 = fmaf(x1, y1, a11);
            }
            __syncthreads();
        }
        const int r0 = i0 + 2 * ty, c0 = j0 + 2 * tx;
        g_bufA[r0 * 256 + c0] = a00;       g_bufA[r0 * 256 + c0 + 1] = a01;
        g_bufA[(r0 + 1) * 256 + c0] = a10; g_bufA[(r0 + 1) * 256 + c0 + 1] = a11;
    } else {
        const int bb = blockIdx.x - 64;
#pragma unroll
        for (int i = 0; i < 16; i++) {
            const int e = bb * 4096 + i * 256 + threadIdx.x;
            const int r = e >> 8, c = e & 255;
            const float v = W[r * W_STRIDE + c];
            const __half h = __float2half_rn(v);
            g_whi[e] = h;
            g_wlo[e] = __float2half_rn(v - __half2float(h));
        }
    }
}

// ---- Kernel 2: sigma. 64 resident CTAs: G^2, G^4, G^8 with atomic grid
// ---- barriers, then CTA0 powiter (fp16 SMEM, 48 iters). lam = sigma^16.
#define SIG_SMEM (131072 + 2048)
__device__ void tile_sq(const float* A, float* C, char* sm) {
    float (*As)[33] = (float(*)[33])sm;
    float (*Bs)[33] = (float(*)[33])(sm + 32 * 33 * 4);
    const int i0 = (blockIdx.x >> 3) * 32, j0 = (blockIdx.x & 7) * 32;
    const int tid = threadIdx.x;
    const int lr = tid >> 3, lc = (tid & 7) * 4;
    const int ty = tid >> 4, tx = tid & 15;
    float a00 = 0, a01 = 0, a10 = 0, a11 = 0;
    for (int kt = 0; kt < 256; kt += 32) {
        float4 av = *(const float4*)&A[(i0 + lr) * 256 + kt + lc];
        float4 bv = *(const float4*)&A[(j0 + lr) * 256 + kt + lc];
        As[lr][lc] = av.x; As[lr][lc + 1] = av.y; As[lr][lc + 2] = av.z; As[lr][lc + 3] = av.w;
        Bs[lr][lc] = bv.x; Bs[lr][lc + 1] = bv.y; Bs[lr][lc + 2] = bv.z; Bs[lr][lc + 3] = bv.w;
        __syncthreads();
#pragma unroll
        for (int k = 0; k < 32; k++) {
            float x0 = As[2 * ty][k], x1 = As[2 * ty + 1][k];
            float y0 = Bs[2 * tx][k], y1 = Bs[2 * tx + 1][k];
            a00 = fmaf(x0, y0, a00); a01 = fmaf(x0, y1, a01);
            a10 = fmaf(x1, y0, a10); a11 = fmaf(x1, y1, a11);
        }
        __syncthreads();
    }
    const int r0 = i0 + 2 * ty, c0 = j0 + 2 * tx;
    C[r0 * 256 + c0] = a00;       C[r0 * 256 + c0 + 1] = a01;
    C[(r0 + 1) * 256 + c0] = a10; C[(r0 + 1) * 256 + c0 + 1] = a11;
}
__device__ __forceinline__ void gsync(unsigned tgt) {
    __syncthreads();
    if (threadIdx.x == 0) {
        __threadfence();
        atomicAdd(&g_bar, 1u);
        while (*(volatile unsigned*)&g_bar < tgt) {}
        __threadfence();
    }
    __syncthreads();
}
__global__ __launch_bounds__(256) void sigma_kernel() {
    extern __shared__ char sm[];
    tile_sq(g_bufA, g_bufB, sm);  gsync(64);    // B = G^2
    tile_sq(g_bufB, g_bufA, sm);  gsync(128);   // A = G^4
    tile_sq(g_bufA, g_bufB, sm);  gsync(192);   // B = G^8
    if (blockIdx.x != 0) return;
    // CTA0: powiter on fp16 H (entries fit fp16; validated R5)
    __half* H = (__half*)sm;
    float* v   = (float*)(sm + 131072);
    float* red = (float*)(sm + 131072 + 1024);
    const int t = threadIdx.x, lane = t & 31, warp = t >> 5;
    for (int i = t; i < 32768; i += 256) {
        const float2 f = ((const float2*)g_bufB)[i];
        ((__half2*)H)[i] = __floats2half2_rn(f.x, f.y);
    }
    v[t] = 0.0625f;
    __syncthreads();
    float lam = 0.f;
    for (int it = 0; it <= 48; it++) {
        float w = 0.f;
#pragma unroll 16
        for (int i = 0; i < 256; i++) w = fmaf(__half2float(H[i * 256 + t]), v[i], w);
        float r = (it == 48) ? w * v[t] : w * w;
#pragma unroll
        for (int off = 16; off > 0; off >>= 1) r += __shfl_xor_sync(0xffffffffu, r, off);
        if (lane == 0) red[warp] = r;
        __syncthreads();
        if (t == 0) { float s = 0.f; for (int k = 0; k < 8; k++) s += red[k]; red[8] = s; }
        __syncthreads();
        if (it == 48) { lam = red[8]; break; }
        const float inv = rsqrtf(red[8]);
        __syncthreads();
        v[t] = w * inv;
        __syncthreads();
    }
    if (t == 0) {
        const double sigma = exp2(log2((double)lam) / 16.0);
        g_scale[0] = (float)(1.0 / (sigma + 1e-6));
        __threadfence();
        g_bar = 0;  // reset for graph replay
    }
}

// ---- Kernel 3: GEMM. 256 thr, 128x64 tile, 2 CTA/SM, fp16x3 split.
// A: in-loop fp32->fp16 hi/lo, 2 stages. W: cp.async, 3 stages, wait_group 1.
#define LDHW 40
#define A_STG 20480u  /* AH(10240)+AL per stage */
#define W_BASE 40960u
#define W_STG 10240u  /* WH(5120)+WL */
#define GEMM_SMEM (40960 + 3 * 10240)

__global__ __launch_bounds__(256, 2)
void gemm_mma_kernel(const float* __restrict__ X, const float* __restrict__ bias,
                     float* __restrict__ out) {
    extern __shared__ __align__(16) char sm[];
    const uint32_t sb = smem_u32(sm);
    const int tid = threadIdx.x;
    const int wid = tid >> 5, lane = tid & 31;
    const int g = lane >> 2, tq = lane & 3;
    const int m0 = blockIdx.y * 128, n0 = blockIdx.x * 64;
    const int wm = (wid >> 1) * 32, wn = (wid & 1) * 32;

    // X loader: 2 thr/row, 16 floats each (2 halves of 8)
    const int arow = tid >> 1, acol = (tid & 1) * 16;
    const float* xg = X + (size_t)(m0 + arow) * 256 + acol;
    const uint32_t aDst = sb + (uint32_t)(arow * LDHW + acol) * 2;
    // W loader: 4 thr/row, 8 halves each
    const int brow = tid >> 2, bseg = (tid & 3) * 8;
    const __half* wh = g_whi + (n0 + brow) * 256 + bseg;
    const __half* wl = g_wlo + (n0 + brow) * 256 + bseg;
    const uint32_t wDst = sb + W_BASE + (uint32_t)(brow * LDHW + bseg) * 2;

    const uint32_t aOff = (uint32_t)(((wm + (lane & 15)) * LDHW) + ((lane >> 4) * 8)) * 2;
    const uint32_t bOff = (uint32_t)(((wn + (lane & 7) + ((lane >> 4) << 3)) * LDHW) +
                                     (((lane >> 3) & 1) * 8)) * 2;

    float acc[2][4][4];
#pragma unroll
    for (int i = 0; i < 2; i++)
#pragma unroll
        for (int j = 0; j < 4; j++)
#pragma unroll
            for (int k = 0; k < 4; k++) acc[i][j][k] = 0.f;

    // prologue: X chunk0 -> A stage0; W chunks 0,1 via cp.async
#pragma unroll
    for (int h = 0; h < 2; h++) {
        float f[8];
        *(float4*)(f)     = *(const float4*)(xg + h * 8);
        *(float4*)(f + 4) = *(const float4*)(xg + h * 8 + 4);
        uint32_t hi[4], lo[4];
        split8(f, hi, lo);
        STS128(aDst + h * 16,         hi[0], hi[1], hi[2], hi[3]);
        STS128(aDst + h * 16 + 10240, lo[0], lo[1], lo[2], lo[3]);
    }
    CP_ASYNC16(wDst, wh);        CP_ASYNC16(wDst + 5120, wl);        CP_COMMIT();
    CP_ASYNC16(wDst + W_STG, wh + 32); CP_ASYNC16(wDst + W_STG + 5120, wl + 32); CP_COMMIT();
    CP_WAIT1();
    __syncthreads();

    for (int c = 0; c < 8; c++) {
        const uint32_t aStg = (uint32_t)(c & 1) * A_STG;
        const uint32_t wStg = W_BASE + (uint32_t)(c % 3) * W_STG;
        float f[16];
        if (c < 7) {
            if (c < 6) {  // W chunk c+2 -> stage (c+2)%3
                const uint32_t nw = sb + W_BASE + (uint32_t)((c + 2) % 3) * W_STG +
                                    (uint32_t)(brow * LDHW + bseg) * 2 - (wDst - wDst);
                const uint32_t d = sb + W_BASE + (uint32_t)((c + 2) % 3) * W_STG +
                                   (uint32_t)(brow * LDHW + bseg) * 2;
                (void)nw;
                CP_ASYNC16(d, wh + (c + 2) * 32);
                CP_ASYNC16(d + 5120, wl + (c + 2) * 32);
                CP_COMMIT();
            }
            const float* xp = xg + (c + 1) * 32;
            *(float4*)(f)      = *(const float4*)(xp);
            *(float4*)(f + 4)  = *(const float4*)(xp + 4);
            *(float4*)(f + 8)  = *(const float4*)(xp + 8);
            *(float4*)(f + 12) = *(const float4*)(xp + 12);
        }
#pragma unroll
        for (int ks = 0; ks < 2; ks++) {
            const uint32_t ko = (uint32_t)ks * 32;
            uint32_t aH[2][4], aL[2][4], bH[8], bL[8];
            LDM_X4(aH[0][0], aH[0][1], aH[0][2], aH[0][3], sb + aStg + aOff + ko);
            LDM_X4(aH[1][0], aH[1][1], aH[1][2], aH[1][3], sb + aStg + aOff + ko + 16 * LDHW * 2);
            LDM_X4(aL[0][0], aL[0][1], aL[0][2], aL[0][3], sb + aStg + 10240 + aOff + ko);
            LDM_X4(aL[1][0], aL[1][1], aL[1][2], aL[1][3], sb + aStg + 10240 + aOff + ko + 16 * LDHW * 2);
            LDM_X4(bH[0], bH[1], bH[2], bH[3], wStg - W_BASE + sb + W_BASE + bOff + ko);
            LDM_X4(bH[4], bH[5], bH[6], bH[7], wStg - W_BASE + sb + W_BASE + bOff + ko + 16 * LDHW * 2);
            LDM_X4(bL[0], bL[1], bL[2], bL[3], wStg - W_BASE + sb + W_BASE + 5120 + bOff + ko);
            LDM_X4(bL[4], bL[5], bL[6], bL[7], wStg - W_BASE + sb + W_BASE + 5120 + bOff + ko + 16 * LDHW * 2);
#pragma unroll
            for (int nt = 0; nt < 4; nt++)
#pragma unroll
                for (int mt = 0; mt < 2; mt++) mma16816(acc[mt][nt], aH[mt], &bH[nt * 2]);
#pragma unroll
            for (int nt = 0; nt < 4; nt++)
#pragma unroll
                for (int mt = 0; mt < 2; mt++) mma16816(acc[mt][nt], aH[mt], &bL[nt * 2]);
#pragma unroll
            for (int nt = 0; nt < 4; nt++)
#pragma unroll
                for (int mt = 0; mt < 2; mt++) mma16816(acc[mt][nt], aL[mt], &bH[nt * 2]);
        }
        if (c < 7) {
            const uint32_t nA = sb + (uint32_t)((c + 1) & 1) * A_STG +
                                (uint32_t)(arow * LDHW + acol) * 2;
            uint32_t hi[4], lo[4];
            split8(f, hi, lo);
            STS128(nA,         hi[0], hi[1], hi[2], hi[3]);
            STS128(nA + 10240, lo[0], lo[1], lo[2], lo[3]);
            split8(f + 8, hi, lo);
            STS128(nA + 16,         hi[0], hi[1], hi[2], hi[3]);
            STS128(nA + 16 + 10240, lo[0], lo[1], lo[2], lo[3]);
            CP_WAIT1();
        }
        __syncthreads();
    }

    const float scale = g_scale[0];
#pragma unroll
    for (int nt = 0; nt < 4; nt++) {
        const int col = n0 + wn + nt * 8 + 2 * tq;
        const float b0 = __ldg(&bias[col]), b1 = __ldg(&bias[col + 1]);
#pragma unroll
        for (int mt = 0; mt < 2; mt++) {
            const int row = m0 + wm + mt * 16 + g;
            float2 o0, o1;
            o0.x = tanh_acc(scale * (acc[mt][nt][0] + b0));
            o0.y = tanh_acc(scale * (acc[mt][nt][1] + b1));
            o1.x = tanh_acc(scale * (acc[mt][nt][2] + b0));
            o1.y = tanh_acc(scale * (acc[mt][nt][3] + b1));
            *(float2*)(out + (size_t)row * 256 + col)       = o0;
            *(float2*)(out + (size_t)(row + 8) * 256 + col) = o1;
        }
    }
}

__global__ void ztail_kernel(float* __restrict__ p, int n) {
    const int i = blockIdx.x * blockDim.x + threadIdx.x;
    if (i < n) p[i] = 0.f;
}

extern "C" void kernel_launch(void* const* d_in, const int* in_sizes, int n_in,
                              void* d_out, int out_size) {
    const float* x = nullptr; const float* W = nullptr; const float* b = nullptr;
    for (int i = 0; i < n_in; i++) {
        const int s = in_sizes[i];
        if (s == 256) b = (const float*)d_in[i];
        else if (s == 131072) W = (const float*)d_in[i];
        else x = (const float*)d_in[i];
    }
    float* out = (float*)d_out;
    cudaFuncSetAttribute(sigma_kernel, cudaFuncAttributeMaxDynamicSharedMemorySize, SIG_SMEM);
    cudaFuncSetAttribute(gemm_mma_kernel, cudaFuncAttributeMaxDynamicSharedMemorySize, GEMM_SMEM);

    prep_kernel<<<80, 256>>>(W);                 // gram + W split
    sigma_kernel<<<64, 256, SIG_SMEM>>>();       // G^8 + powiter -> g_scale
    const int main_elems = M_TOTAL * 256;
    if (out_size > main_elems) {
        const int tail = out_size - main_elems;
        ztail_kernel<<<(tail + 255) / 256, 256>>>(out + main_elems, tail);
    }
    gemm_mma_kernel<<<dim3(4, 512), 256, GEMM_SMEM>>>(x, b, out);  // profiled slot
}